// round 4
// baseline (speedup 1.0000x reference)
#include <cuda_runtime.h>
#include <math.h>

// DGPLoss fused single-kernel, smem-cached centers:
//   seg_feat: [4, 64, 512, 512] fp32   (d_in[0])
//   dep_true: [4, 1, 512, 512]  fp32   (d_in[1])
//   out[0]  : scalar fp32
//
// Block = one image row h (0..509) x batch. Preload the row-band's 102 patch
// centers for all 64 channels into smem (25.5KB), then the main loop is a pure
// stream of independent LDG.128 + LDS (no global latency in the chain).
// One thread = 4 adjacent pixels. Last block (ticket) reduces 2040 partials.

#define EPSF 1e-8f
#define EPS2 1e-16f
#define CS   262144           // 512*512
#define NH   510
#define NBAT 4
#define NPART (NH * NBAT)     // 2040

__device__ float2       g_part[NPART];
__device__ unsigned int g_ticket;    // zero-init; reset by last block each run

__global__ __launch_bounds__(128, 8)
void dgp_fused(const float* __restrict__ seg, const float* __restrict__ dep,
               float* __restrict__ out)
{
    __shared__ float s_ctr[64][104];  // [channel][patch] centers (102 used)
    __shared__ float s_dc[104];       // depth centers
    __shared__ float2 sw[4];
    __shared__ bool   isLast;

    const int tid = threadIdx.x;
    const int h   = blockIdx.x;           // 0..509
    const int b   = blockIdx.y;           // 0..3
    const int hc  = (h / 5) * 5 + 2;

    const int segBase = b * (64 * CS);    // fits int32
    const int depBase = b * CS;

    // ---- preload centers: 64*102 = 6528 floats, 51 iters/thread ----
    {
        const float* __restrict__ crow = seg + segBase + hc * 512 + 2;
        #pragma unroll 4
        for (int idx = tid; idx < 64 * 102; idx += 128) {
            const int c = idx / 102;
            const int p = idx - c * 102;
            s_ctr[c][p] = crow[c * CS + p * 5];
        }
        if (tid < 102) s_dc[tid] = dep[depBase + hc * 512 + tid * 5 + 2];
    }
    __syncthreads();

    // ---- per-thread pixel quad ----
    const int w0 = tid << 2;              // 0..508
    const int pA = w0 / 5;
    const int pB = (w0 + 3) / 5;          // may be 102 for w0=508 (masked out)
    const bool sB1 = ((w0 + 1) / 5) != pA;
    const bool sB2 = ((w0 + 2) / 5) != pA;
    const bool sB3 = (pB != pA);

    const float4* __restrict__ pix = (const float4*)(seg + segBase + h * 512 + w0);

    float a0 = 0.f, a1 = 0.f, a2 = 0.f, a3 = 0.f;
    #pragma unroll 8
    for (int c = 0; c < 64; ++c) {
        const float4 p  = pix[c * (CS / 4)];
        const float  qA = s_ctr[c][pA];
        const float  qB = s_ctr[c][pB];
        const float  q1 = sB1 ? qB : qA;
        const float  q2 = sB2 ? qB : qA;
        const float  q3 = sB3 ? qB : qA;
        float d;
        d = qA - p.x; a0 = fmaf(d, d, a0);
        d = q1 - p.y; a1 = fmaf(d, d, a1);
        d = q2 - p.z; a2 = fmaf(d, d, a2);
        d = q3 - p.w; a3 = fmaf(d, d, a3);
    }

    // ---- depth + mask + local sum ----
    const float4 dq  = *(const float4*)(dep + depBase + h * 512 + w0);
    const float  dcA = s_dc[pA];
    const float  dcB = s_dc[pB];
    const int    wcA = pA * 5 + 2;
    const int    wcB = pB * 5 + 2;

    const float dcv[4] = { dcA, sB1 ? dcB : dcA, sB2 ? dcB : dcA, sB3 ? dcB : dcA };
    const int   wcv[4] = { wcA, sB1 ? wcB : wcA, sB2 ? wcB : wcA, sB3 ? wcB : wcA };
    const float av [4] = { a0, a1, a2, a3 };
    const float dpv[4] = { dq.x, dq.y, dq.z, dq.w };

    float sum = 0.f, cnt = 0.f;
    #pragma unroll
    for (int k = 0; k < 4; ++k) {
        const float dd = fabsf(dcv[k] - dpv[k]);
        const bool ic  = (h == hc) && (w0 + k == wcv[k]);
        const bool m   = (dd > EPSF) && (av[k] > EPS2) && (dpv[k] > EPSF) &&
                         !ic && (w0 + k < 510);
        if (m) {
            sum += __expf(-fmaf(dd, 0.1f, av[k]));
            cnt += 1.f;
        }
    }

    // ---- intra-block reduce ----
    #pragma unroll
    for (int o = 16; o > 0; o >>= 1) {
        sum += __shfl_down_sync(0xFFFFFFFFu, sum, o);
        cnt += __shfl_down_sync(0xFFFFFFFFu, cnt, o);
    }
    const int lane = tid & 31;
    const int wid  = tid >> 5;
    if (lane == 0) sw[wid] = make_float2(sum, cnt);
    __syncthreads();

    if (tid == 0) {
        const float2 t0 = sw[0], t1 = sw[1], t2 = sw[2], t3 = sw[3];
        g_part[blockIdx.x + NH * blockIdx.y] =
            make_float2(t0.x + t1.x + t2.x + t3.x, t0.y + t1.y + t2.y + t3.y);
        __threadfence();
        const unsigned t = atomicAdd(&g_ticket, 1u);
        isLast = (t == NPART - 1);
    }
    __syncthreads();

    // ---- final deterministic reduction by the last block ----
    if (isLast) {
        __threadfence();
        float s = 0.f, c = 0.f;
        #pragma unroll 4
        for (int i = tid; i < NPART; i += 128) {
            const float2 v = g_part[i];
            s += v.x; c += v.y;
        }
        #pragma unroll
        for (int o = 16; o > 0; o >>= 1) {
            s += __shfl_down_sync(0xFFFFFFFFu, s, o);
            c += __shfl_down_sync(0xFFFFFFFFu, c, o);
        }
        if (lane == 0) sw[wid] = make_float2(s, c);
        __syncthreads();
        if (tid == 0) {
            const float2 t0 = sw[0], t1 = sw[1], t2 = sw[2], t3 = sw[3];
            out[0] = (t0.x + t1.x + t2.x + t3.x) /
                     fmaxf(t0.y + t1.y + t2.y + t3.y, 1.0f);
            g_ticket = 0u;   // reset for next graph replay
        }
    }
}

extern "C" void kernel_launch(void* const* d_in, const int* in_sizes, int n_in,
                              void* d_out, int out_size) {
    const float* seg = (const float*)d_in[0];   // [4,64,512,512]
    const float* dep = (const float*)d_in[1];   // [4,1,512,512]
    float* out = (float*)d_out;

    dim3 grid(NH, NBAT);
    dgp_fused<<<grid, 128>>>(seg, dep, out);
}

// round 5
// speedup vs baseline: 1.7734x; 1.7734x over previous
#include <cuda_runtime.h>
#include <math.h>

// DGPLoss fused single-kernel, whole-band blocks:
//   seg_feat: [4, 64, 512, 512] fp32   (d_in[0])
//   dep_true: [4, 1, 512, 512]  fp32   (d_in[1])
//   out[0]  : scalar fp32
//
// Block = one 5-row patch band (102 bands) x batch. 640 threads = 5 rows x
// 128 threads, one thread = 4 adjacent pixels (LDG.128). The row-2 warps'
// own pixel loads ARE the center row: they extract their center element into
// smem (102 floats/channel), so the channel loop does exactly the compulsory
// loads and nothing else. Double-buffered centers, one __syncthreads/channel,
// pixel load prefetched one channel ahead (issued right after the barrier).
// Ticket-elected last block does the deterministic final reduction.

#define EPSF 1e-8f
#define EPS2 1e-16f
#define CS   262144              // 512*512
#define NBANDS 102
#define NBAT 4
#define NPART (NBANDS * NBAT)    // 408

__device__ float2       g_part[NPART];
__device__ unsigned int g_ticket;   // zero-init; reset by last block each run

__device__ __forceinline__ float selq(float4 v, int off) {
    const float lo = (off & 1) ? v.y : v.x;
    const float hi = (off & 1) ? v.w : v.z;
    return (off & 2) ? hi : lo;
}

__global__ __launch_bounds__(640, 3)
void dgp_fused(const float* __restrict__ seg, const float* __restrict__ dep,
               float* __restrict__ out)
{
    __shared__ float  s_c[2][104];   // double-buffered per-channel centers
    __shared__ float  s_dc[104];     // depth centers
    __shared__ float2 s_red[20];
    __shared__ bool   isLast;

    const int tid = threadIdx.x;
    const int r   = tid >> 7;        // row within band: 0..4
    const int wl  = tid & 127;
    const int w0  = wl << 2;         // 0..508
    const int j   = blockIdx.x;      // band 0..101
    const int b   = blockIdx.y;      // batch 0..3
    const int h   = j * 5 + r;

    const int  pA  = w0 / 5;
    const int  pB  = (w0 + 3) / 5;   // may be 102 (pad slot, masked)
    const bool sB1 = ((w0 + 1) / 5) != pA;
    const bool sB2 = ((w0 + 2) / 5) != pA;
    const bool sB3 = (pB != pA);

    // center-extraction constants: the one column in [w0,w0+3] with col%5==2
    const int  rem = w0 - pA * 5;
    const int  off = (7 - rem) % 5;          // 0..4; 4 => no center in quad
    const bool has = (r == 2) && (off < 4);
    const int  cp  = (w0 + off) / 5;         // patch index of that center

    // zero the pad slots once (reads of pad are masked, but keep them finite)
    if (tid < 2)               s_c[0][102 + tid] = 0.f;
    else if (tid < 4)          s_c[1][100 + tid] = 0.f;
    else if (tid < 6)          s_dc[98 + tid]    = 0.f;

    const float4* __restrict__ pix =
        (const float4*)(seg + (size_t)b * 64 * CS + (size_t)h * 512 + w0);

    float a0 = 0.f, a1 = 0.f, a2 = 0.f, a3 = 0.f;
    float4 pc = pix[0];

    #pragma unroll 4
    for (int g = 0; g < 64; ++g) {
        const int buf = g & 1;
        if (has) s_c[buf][cp] = selq(pc, off);
        __syncthreads();
        // prefetch next channel (issued while this channel computes)
        float4 pn = pc;
        if (g < 63) pn = pix[(g + 1) * (CS / 4)];

        const float qA = s_c[buf][pA];
        const float qB = s_c[buf][pB];
        const float q1 = sB1 ? qB : qA;
        const float q2 = sB2 ? qB : qA;
        const float q3 = sB3 ? qB : qA;
        float d;
        d = qA - pc.x; a0 = fmaf(d, d, a0);
        d = q1 - pc.y; a1 = fmaf(d, d, a1);
        d = q2 - pc.z; a2 = fmaf(d, d, a2);
        d = q3 - pc.w; a3 = fmaf(d, d, a3);
        pc = pn;
    }

    // ---- depth branch ----
    const float4 dq = *(const float4*)(dep + (size_t)b * CS + (size_t)h * 512 + w0);
    if (has) s_dc[cp] = selq(dq, off);
    __syncthreads();

    const float dcA = s_dc[pA];
    const float dcB = s_dc[pB];
    const int   wcA = pA * 5 + 2;
    const int   wcB = pB * 5 + 2;

    const float dcv[4] = { dcA, sB1 ? dcB : dcA, sB2 ? dcB : dcA, sB3 ? dcB : dcA };
    const int   wcv[4] = { wcA, sB1 ? wcB : wcA, sB2 ? wcB : wcA, sB3 ? wcB : wcA };
    const float av [4] = { a0, a1, a2, a3 };
    const float dpv[4] = { dq.x, dq.y, dq.z, dq.w };

    float sum = 0.f, cnt = 0.f;
    #pragma unroll
    for (int k = 0; k < 4; ++k) {
        const float dd = fabsf(dcv[k] - dpv[k]);
        const bool ic  = (r == 2) && (w0 + k == wcv[k]);
        const bool m   = (dd > EPSF) && (av[k] > EPS2) && (dpv[k] > EPSF) &&
                         !ic && (w0 + k < 510);
        if (m) {
            sum += __expf(-fmaf(dd, 0.1f, av[k]));
            cnt += 1.f;
        }
    }

    // ---- block reduce (20 warps) ----
    #pragma unroll
    for (int o = 16; o > 0; o >>= 1) {
        sum += __shfl_down_sync(0xFFFFFFFFu, sum, o);
        cnt += __shfl_down_sync(0xFFFFFFFFu, cnt, o);
    }
    const int lane = tid & 31;
    const int wid  = tid >> 5;
    if (lane == 0) s_red[wid] = make_float2(sum, cnt);
    __syncthreads();

    if (wid == 0) {
        float s = (lane < 20) ? s_red[lane].x : 0.f;
        float c = (lane < 20) ? s_red[lane].y : 0.f;
        #pragma unroll
        for (int o = 16; o > 0; o >>= 1) {
            s += __shfl_down_sync(0xFFFFFFFFu, s, o);
            c += __shfl_down_sync(0xFFFFFFFFu, c, o);
        }
        if (lane == 0) {
            g_part[j + NBANDS * b] = make_float2(s, c);
            __threadfence();
            const unsigned t = atomicAdd(&g_ticket, 1u);
            isLast = (t == NPART - 1);
        }
    }
    __syncthreads();

    // ---- final deterministic reduction by the last block ----
    if (isLast) {
        __threadfence();
        float s = 0.f, c = 0.f;
        if (tid < NPART) {               // 408 < 640: one partial per thread
            const float2 v = g_part[tid];
            s = v.x; c = v.y;
        }
        #pragma unroll
        for (int o = 16; o > 0; o >>= 1) {
            s += __shfl_down_sync(0xFFFFFFFFu, s, o);
            c += __shfl_down_sync(0xFFFFFFFFu, c, o);
        }
        __syncthreads();                 // s_red reuse
        if (lane == 0) s_red[wid] = make_float2(s, c);
        __syncthreads();
        if (wid == 0) {
            float ts = (lane < 20) ? s_red[lane].x : 0.f;
            float tc = (lane < 20) ? s_red[lane].y : 0.f;
            #pragma unroll
            for (int o = 16; o > 0; o >>= 1) {
                ts += __shfl_down_sync(0xFFFFFFFFu, ts, o);
                tc += __shfl_down_sync(0xFFFFFFFFu, tc, o);
            }
            if (lane == 0) {
                out[0] = ts / fmaxf(tc, 1.0f);
                g_ticket = 0u;           // reset for next graph replay
            }
        }
    }
}

extern "C" void kernel_launch(void* const* d_in, const int* in_sizes, int n_in,
                              void* d_out, int out_size) {
    const float* seg = (const float*)d_in[0];   // [4,64,512,512]
    const float* dep = (const float*)d_in[1];   // [4,1,512,512]
    float* out = (float*)d_out;

    dim3 grid(NBANDS, NBAT);
    dgp_fused<<<grid, 640>>>(seg, dep, out);
}